// round 5
// baseline (speedup 1.0000x reference)
#include <cuda_runtime.h>
#include <cuda.h>
#include <cuda_bf16.h>
#include <cstdint>
#include <cstddef>

// Problem dims (fixed by the dataset)
#define BATCH 4
#define MDIM 2048
#define NDIM 2048
#define KDIM 2048

// GEMM tiling
#define TILE_M 128
#define TILE_N 128
#define KC 128                   // K per chunk: 128 int8 = 128B row = SW128 atom
#define NCHUNK (KDIM / KC)       // 16
#define STAGES 3

// Per-stage SMEM layout: A1,A2,B1,B2 int8 tiles (128 rows x 128 bytes each)
#define OFF_A1 0
#define OFF_A2 16384
#define OFF_B1 32768
#define OFF_B2 49152
#define STAGE_BYTES 65536
#define SMEM_CTRL 1024
#define SMEM_TOTAL (SMEM_CTRL + STAGES * STAGE_BYTES)   // 197632

// ---------------------------------------------------------------------------
// Scratch: int8 digit splits. A [B,M,K]; B transposed to [B,N,K] (K-major).
// Per-row scales: sa = rowmax/127 so a = sa*(A1 + A2/128).
// ---------------------------------------------------------------------------
__device__ alignas(1024) int8_t g_A1[(size_t)BATCH * MDIM * KDIM];
__device__ alignas(1024) int8_t g_A2[(size_t)BATCH * MDIM * KDIM];
__device__ alignas(1024) int8_t g_B1[(size_t)BATCH * NDIM * KDIM];
__device__ alignas(1024) int8_t g_B2[(size_t)BATCH * NDIM * KDIM];
__device__ float g_scaleA[(size_t)BATCH * MDIM];
__device__ float g_scaleB[(size_t)BATCH * NDIM];

// ---------------------------------------------------------------------------
// PTX helpers — sm_90-class only (NO 'a'-suffix; ptxas target is sm_103)
// ---------------------------------------------------------------------------
__device__ __forceinline__ uint32_t smem_u32(const void* p) {
    uint32_t a;
    asm("{ .reg .u64 t; cvta.to.shared.u64 t, %1; cvt.u32.u64 %0, t; }"
        : "=r"(a) : "l"(p));
    return a;
}

#define MBARRIER_INIT(addr, cnt) \
    asm volatile("mbarrier.init.shared.b64 [%0], %1;" :: "r"(addr), "r"(cnt) : "memory")

#define MBARRIER_EXPECT_TX(addr, bytes) \
    asm volatile("mbarrier.arrive.expect_tx.shared.b64 _, [%0], %1;" \
                 :: "r"(addr), "r"(bytes) : "memory")

#define MBAR_WAIT(addr, parity) do {                                          \
    asm volatile(                                                             \
        "{\n\t.reg .pred P1;\n\t"                                             \
        "WAIT_LOOP_%=:\n\t"                                                   \
        "mbarrier.try_wait.parity.acquire.cta.shared::cta.b64 P1, [%0], %1, 0x989680;\n\t" \
        "@P1 bra.uni WAIT_DONE_%=;\n\t"                                       \
        "bra.uni WAIT_LOOP_%=;\n\t"                                           \
        "WAIT_DONE_%=:\n\t}"                                                  \
        :: "r"((uint32_t)(addr)), "r"((uint32_t)(parity)) : "memory");        \
} while (0)

__device__ __forceinline__ void tma2d(uint32_t smem_dst, const CUtensorMap* map,
                                      int x, int y, uint32_t mbar) {
    asm volatile(
        "cp.async.bulk.tensor.2d.shared::cta.global.tile.mbarrier::complete_tx::bytes "
        "[%0], [%1, {%2, %3}], [%4];"
        :: "r"(smem_dst), "l"(map), "r"(x), "r"(y), "r"(mbar)
        : "memory");
}

__device__ __forceinline__ void ldsm_x4(uint32_t* r, uint32_t addr) {
    asm volatile("ldmatrix.sync.aligned.m8n8.x4.shared.b16 {%0,%1,%2,%3}, [%4];"
                 : "=r"(r[0]), "=r"(r[1]), "=r"(r[2]), "=r"(r[3]) : "r"(addr));
}

// m16n8k32 int8 MMA, s32 accumulate
__device__ __forceinline__ void mma_s8(int* d, const uint32_t* a,
                                       uint32_t b0, uint32_t b1) {
    asm volatile(
        "mma.sync.aligned.m16n8k32.row.col.s32.s8.s8.s32 "
        "{%0,%1,%2,%3}, {%4,%5,%6,%7}, {%8,%9}, {%0,%1,%2,%3};"
        : "+r"(d[0]), "+r"(d[1]), "+r"(d[2]), "+r"(d[3])
        : "r"(a[0]), "r"(a[1]), "r"(a[2]), "r"(a[3]), "r"(b0), "r"(b1));
}

// ---------------------------------------------------------------------------
// Scale kernels
// ---------------------------------------------------------------------------
__global__ void maxA_kernel(const float* __restrict__ a) {
    const size_t row = blockIdx.x;           // b*M + m
    const float* p = a + row * KDIM;
    float m = 0.0f;
    for (int i = threadIdx.x; i < KDIM; i += 256) m = fmaxf(m, fabsf(p[i]));
    __shared__ float red[8];
#pragma unroll
    for (int o = 16; o; o >>= 1) m = fmaxf(m, __shfl_xor_sync(~0u, m, o));
    if ((threadIdx.x & 31) == 0) red[threadIdx.x >> 5] = m;
    __syncthreads();
    if (threadIdx.x == 0) {
        for (int j = 1; j < 8; j++) m = fmaxf(m, red[j]);
        g_scaleA[row] = fmaxf(m, 1e-30f) * (1.0f / 127.0f);
    }
}

__global__ void maxB_kernel(const float* __restrict__ bsrc) {
    const int n = blockIdx.x * 32 + threadIdx.x;
    const int b = blockIdx.y;
    const float* p = bsrc + (size_t)b * KDIM * NDIM + n;
    float m = 0.0f;
    for (int k = threadIdx.y; k < KDIM; k += 8)
        m = fmaxf(m, fabsf(p[(size_t)k * NDIM]));
    __shared__ float red[8][32];
    red[threadIdx.y][threadIdx.x] = m;
    __syncthreads();
    if (threadIdx.y == 0) {
#pragma unroll
        for (int j = 1; j < 8; j++) m = fmaxf(m, red[j][threadIdx.x]);
        g_scaleB[b * NDIM + n] = fmaxf(m, 1e-30f) * (1.0f / 127.0f);
    }
}

// ---------------------------------------------------------------------------
// Quantization kernels
// ---------------------------------------------------------------------------
__device__ __forceinline__ void quant2(float v, float inv, int8_t& d1, int8_t& d2) {
    float x = v * inv;                 // |x| <= 127
    float q1 = rintf(x);
    float q2 = rintf((x - q1) * 128.0f);   // in [-64, 64]
    d1 = (int8_t)(int)q1;
    d2 = (int8_t)(int)q2;
}

__global__ void cvtAq_kernel(const float* __restrict__ a) {
    const size_t row = blockIdx.x;           // b*M + m
    const float inv = 1.0f / g_scaleA[row];
    const float4* src = (const float4*)(a + row * KDIM);
    char4* o1 = (char4*)(g_A1 + row * KDIM);
    char4* o2 = (char4*)(g_A2 + row * KDIM);
    for (int i = threadIdx.x; i < KDIM / 4; i += 256) {
        float4 v = src[i];
        char4 c1, c2;
        quant2(v.x, inv, c1.x, c2.x);
        quant2(v.y, inv, c1.y, c2.y);
        quant2(v.z, inv, c1.z, c2.z);
        quant2(v.w, inv, c1.w, c2.w);
        o1[i] = c1;
        o2[i] = c2;
    }
}

// B[b][k][n] -> Bt[b][n][k] int8 digits, 32x32 tile transpose
__global__ void cvtBq_kernel(const float* __restrict__ bsrc) {
    __shared__ float t[32][33];
    const int b = blockIdx.z;
    const int n0 = blockIdx.x * 32;
    const int k0 = blockIdx.y * 32;
    const int tid = threadIdx.x;
    const float* src = bsrc + (size_t)b * KDIM * NDIM;

    const int rr = tid >> 3, cc = (tid & 7) * 4;     // read: row k0+rr, 4 n's
    float4 v = *(const float4*)&src[(size_t)(k0 + rr) * NDIM + n0 + cc];
    t[rr][cc + 0] = v.x; t[rr][cc + 1] = v.y;
    t[rr][cc + 2] = v.z; t[rr][cc + 3] = v.w;
    __syncthreads();

    const int n = tid >> 3, kq = tid & 7;            // write: row n, char4 at k
    const float inv = 1.0f / g_scaleB[b * NDIM + n0 + n];
    char4 c1, c2;
    quant2(t[kq * 4 + 0][n], inv, c1.x, c2.x);
    quant2(t[kq * 4 + 1][n], inv, c1.y, c2.y);
    quant2(t[kq * 4 + 2][n], inv, c1.z, c2.z);
    quant2(t[kq * 4 + 3][n], inv, c1.w, c2.w);
    const size_t off = (size_t)b * NDIM * KDIM + (size_t)(n0 + n) * KDIM + k0 + kq * 4;
    *(char4*)&g_B1[off] = c1;
    *(char4*)&g_B2[off] = c2;
}

// ---------------------------------------------------------------------------
// GEMM: 128x128 tile/CTA, int8 2-digit 3-term, TMA(SW128)+ldmatrix+mma.s8
// 256 threads = 8 warps, warp grid 4(M) x 2(N), warp tile 32x64.
// ---------------------------------------------------------------------------
__global__ void __launch_bounds__(256, 1) gemm_kernel(
    const __grid_constant__ CUtensorMap mA1,
    const __grid_constant__ CUtensorMap mA2,
    const __grid_constant__ CUtensorMap mB1,
    const __grid_constant__ CUtensorMap mB2,
    float* __restrict__ C)
{
    extern __shared__ char smem[];
    const uint32_t sb = smem_u32(smem);
    const int tid = threadIdx.x;
    const int wid = tid >> 5;
    const int lane = tid & 31;
    const int warpM = wid & 3;        // 4 groups of 32 rows
    const int warpN = wid >> 2;       // 2 groups of 64 cols

    const int tn = blockIdx.x;
    const int tm = blockIdx.y;
    const int bb = blockIdx.z;

    if (tid == 0) {
#pragma unroll
        for (int s = 0; s < STAGES; s++) MBARRIER_INIT(sb + 8 * s, 1);
        asm volatile("fence.proxy.async.shared::cta;" ::: "memory");
    }
    __syncthreads();

    const int rowA = bb * MDIM + tm * TILE_M;
    const int rowB = bb * NDIM + tn * TILE_N;

    if (tid == 0) {
#pragma unroll
        for (int s = 0; s < STAGES; s++) {
            uint32_t st = sb + SMEM_CTRL + s * STAGE_BYTES;
            MBARRIER_EXPECT_TX(sb + 8 * s, (uint32_t)STAGE_BYTES);
            tma2d(st + OFF_A1, &mA1, s * KC, rowA, sb + 8 * s);
            tma2d(st + OFF_A2, &mA2, s * KC, rowA, sb + 8 * s);
            tma2d(st + OFF_B1, &mB1, s * KC, rowB, sb + 8 * s);
            tma2d(st + OFF_B2, &mB2, s * KC, rowB, sb + 8 * s);
        }
    }

    // ldmatrix addressing. SW128 swizzle: XOR byte-offset bits[6:4] with row&7.
    const uint32_t xorv = (uint32_t)((lane & 7) << 4);

    // A (m16 x k32): lanes 0-15 -> rows 0-15 k+0; lanes 16-31 -> rows 0-15 k+16
    const int aRowLane = lane & 15;
    const uint32_t aKoff = (uint32_t)((lane >> 4) * 16);
    uint32_t aRowOff[2];
#pragma unroll
    for (int mt = 0; mt < 2; mt++)
        aRowOff[mt] = (uint32_t)(warpM * 32 + mt * 16 + aRowLane) * 128;

    // B (two n8 tiles per x4): lanes0-7 nt_e k+0 | 8-15 nt_e k+16 | 16-23 nt_o k+0 | 24-31 nt_o k+16
    const int bRowLane = (lane & 7) + ((lane >> 4) << 3);
    const uint32_t bKoff = (uint32_t)(((lane >> 3) & 1) * 16);
    uint32_t bRowOff[4];
#pragma unroll
    for (int np = 0; np < 4; np++)
        bRowOff[np] = (uint32_t)(warpN * 64 + np * 16 + bRowLane) * 128;

    uint32_t aKpart[4], bKpart[4];
#pragma unroll
    for (int ks = 0; ks < 4; ks++) {
        aKpart[ks] = ((uint32_t)(ks * 32) + aKoff) ^ xorv;
        bKpart[ks] = ((uint32_t)(ks * 32) + bKoff) ^ xorv;
    }

    int acc1[2][8][4], acc2[2][8][4];
#pragma unroll
    for (int mt = 0; mt < 2; mt++)
#pragma unroll
        for (int nt = 0; nt < 8; nt++)
#pragma unroll
            for (int i = 0; i < 4; i++) { acc1[mt][nt][i] = 0; acc2[mt][nt][i] = 0; }

    int pf[STAGES] = {0, 0, 0};

    for (int c = 0; c < NCHUNK; c++) {
        const int s = c % STAGES;
        const uint32_t st = sb + SMEM_CTRL + s * STAGE_BYTES;

        MBAR_WAIT(sb + 8 * s, pf[s]);
        pf[s] ^= 1;
        __syncthreads();
        if (tid == 0 && c >= 1 && c + 2 < NCHUNK) {
            const int rs = (c + 2) % STAGES;
            const uint32_t rst = sb + SMEM_CTRL + rs * STAGE_BYTES;
            const int kk = (c + 2) * KC;
            MBARRIER_EXPECT_TX(sb + 8 * rs, (uint32_t)STAGE_BYTES);
            tma2d(rst + OFF_A1, &mA1, kk, rowA, sb + 8 * rs);
            tma2d(rst + OFF_A2, &mA2, kk, rowA, sb + 8 * rs);
            tma2d(rst + OFF_B1, &mB1, kk, rowB, sb + 8 * rs);
            tma2d(rst + OFF_B2, &mB2, kk, rowB, sb + 8 * rs);
        }

#pragma unroll
        for (int ks = 0; ks < 4; ks++) {
            uint32_t a1[2][4], a2[2][4];     // a-frags per mt per digit
            uint32_t b1[4][4], b2[4][4];     // per ntpair: {b0_e,b1_e,b0_o,b1_o}
#pragma unroll
            for (int mt = 0; mt < 2; mt++) {
                ldsm_x4(a1[mt], st + OFF_A1 + aRowOff[mt] + aKpart[ks]);
                ldsm_x4(a2[mt], st + OFF_A2 + aRowOff[mt] + aKpart[ks]);
            }
#pragma unroll
            for (int np = 0; np < 4; np++) {
                ldsm_x4(b1[np], st + OFF_B1 + bRowOff[np] + bKpart[ks]);
                ldsm_x4(b2[np], st + OFF_B2 + bRowOff[np] + bKpart[ks]);
            }
#pragma unroll
            for (int mt = 0; mt < 2; mt++) {
#pragma unroll
                for (int nt = 0; nt < 8; nt++) {
                    const int np = nt >> 1;
                    const int o = (nt & 1) * 2;     // {0,1} or {2,3}
                    mma_s8(acc1[mt][nt], a1[mt], b1[np][o], b1[np][o + 1]);
                    mma_s8(acc2[mt][nt], a1[mt], b2[np][o], b2[np][o + 1]);
                    mma_s8(acc2[mt][nt], a2[mt], b1[np][o], b1[np][o + 1]);
                }
            }
        }
    }

    // Epilogue: C = sa*sb*(acc1 + acc2/128)
    const int cRow0 = tm * TILE_M + warpM * 32 + (lane >> 2);
    const int cCol0 = tn * TILE_N + warpN * 64 + (lane & 3) * 2;
    float* Cb = C + (size_t)bb * MDIM * NDIM;
    const float* sBp = g_scaleB + bb * NDIM;
    const float* sAp = g_scaleA + bb * MDIM;

    float sB[8][2];
#pragma unroll
    for (int nt = 0; nt < 8; nt++) {
        sB[nt][0] = sBp[cCol0 + nt * 8];
        sB[nt][1] = sBp[cCol0 + nt * 8 + 1];
    }
#pragma unroll
    for (int mt = 0; mt < 2; mt++) {
        const int r0 = cRow0 + mt * 16;
        const float sa0 = sAp[r0];
        const float sa1 = sAp[r0 + 8];
        float* rp0 = Cb + (size_t)r0 * NDIM + cCol0;
        float* rp1 = Cb + (size_t)(r0 + 8) * NDIM + cCol0;
#pragma unroll
        for (int nt = 0; nt < 8; nt++) {
            float v0 = sa0 * sB[nt][0] *
                ((float)acc1[mt][nt][0] + (float)acc2[mt][nt][0] * 0.0078125f);
            float v1 = sa0 * sB[nt][1] *
                ((float)acc1[mt][nt][1] + (float)acc2[mt][nt][1] * 0.0078125f);
            float v2 = sa1 * sB[nt][0] *
                ((float)acc1[mt][nt][2] + (float)acc2[mt][nt][2] * 0.0078125f);
            float v3 = sa1 * sB[nt][1] *
                ((float)acc1[mt][nt][3] + (float)acc2[mt][nt][3] * 0.0078125f);
            *reinterpret_cast<float2*>(rp0 + nt * 8) = make_float2(v0, v1);
            *reinterpret_cast<float2*>(rp1 + nt * 8) = make_float2(v2, v3);
        }
    }
}

// ---------------------------------------------------------------------------
// Host launch
// ---------------------------------------------------------------------------
typedef CUresult (*PFN_tmap_encode)(
    CUtensorMap*, CUtensorMapDataType, cuuint32_t, void*,
    const cuuint64_t*, const cuuint64_t*, const cuuint32_t*, const cuuint32_t*,
    CUtensorMapInterleave, CUtensorMapSwizzle, CUtensorMapL2promotion,
    CUtensorMapFloatOOBfill);

static void make_map_s8(PFN_tmap_encode enc, CUtensorMap* m, void* base,
                        cuuint64_t dim0, cuuint64_t dim1,
                        cuuint32_t box0, cuuint32_t box1) {
    cuuint64_t gd[2] = {dim0, dim1};
    cuuint64_t gs[1] = {dim0};
    cuuint32_t bd[2] = {box0, box1};
    cuuint32_t es[2] = {1, 1};
    enc(m, CU_TENSOR_MAP_DATA_TYPE_UINT8, 2, base, gd, gs, bd, es,
        CU_TENSOR_MAP_INTERLEAVE_NONE, CU_TENSOR_MAP_SWIZZLE_128B,
        CU_TENSOR_MAP_L2_PROMOTION_L2_128B, CU_TENSOR_MAP_FLOAT_OOB_FILL_NONE);
}

extern "C" void kernel_launch(void* const* d_in, const int* in_sizes, int n_in,
                              void* d_out, int out_size) {
    (void)in_sizes; (void)n_in; (void)out_size;
    const float* A = (const float*)d_in[0];
    const float* B = (const float*)d_in[1];
    float* C = (float*)d_out;

    maxA_kernel<<<BATCH * MDIM, 256>>>(A);
    maxB_kernel<<<dim3(NDIM / 32, BATCH), dim3(32, 8)>>>(B);
    cvtAq_kernel<<<BATCH * MDIM, 256>>>(A);
    cvtBq_kernel<<<dim3(NDIM / 32, KDIM / 32, BATCH), 256>>>(B);

    void *pA1 = nullptr, *pA2 = nullptr, *pB1 = nullptr, *pB2 = nullptr;
    cudaGetSymbolAddress(&pA1, g_A1);
    cudaGetSymbolAddress(&pA2, g_A2);
    cudaGetSymbolAddress(&pB1, g_B1);
    cudaGetSymbolAddress(&pB2, g_B2);

    void* fn = nullptr;
    cudaDriverEntryPointQueryResult qr;
    cudaGetDriverEntryPoint("cuTensorMapEncodeTiled", &fn, cudaEnableDefault, &qr);
    if (!fn) return;
    PFN_tmap_encode enc = (PFN_tmap_encode)fn;

    CUtensorMap mA1, mA2, mB1, mB2;
    make_map_s8(enc, &mA1, pA1, KDIM, (cuuint64_t)BATCH * MDIM, KC, TILE_M);
    make_map_s8(enc, &mA2, pA2, KDIM, (cuuint64_t)BATCH * MDIM, KC, TILE_M);
    make_map_s8(enc, &mB1, pB1, KDIM, (cuuint64_t)BATCH * NDIM, KC, TILE_N);
    make_map_s8(enc, &mB2, pB2, KDIM, (cuuint64_t)BATCH * NDIM, KC, TILE_N);

    cudaFuncSetAttribute(gemm_kernel, cudaFuncAttributeMaxDynamicSharedMemorySize,
                         SMEM_TOTAL);
    gemm_kernel<<<dim3(NDIM / TILE_N, MDIM / TILE_M, BATCH), 256, SMEM_TOTAL>>>(
        mA1, mA2, mB1, mB2, C);
}

// round 6
// speedup vs baseline: 2.8799x; 2.8799x over previous
#include <cuda_runtime.h>
#include <cuda.h>
#include <cuda_fp16.h>
#include <cstdint>
#include <cstddef>

// Problem dims (fixed by the dataset)
#define BATCH 4
#define MDIM 2048
#define NDIM 2048
#define KDIM 2048

// GEMM tiling
#define TILE_M 128
#define TILE_N 128
#define KC 64                    // K per chunk: 64 fp16 = 128B row = SW128 atom
#define NCHUNK (KDIM / KC)       // 32
#define STAGES 3

// Per-stage SMEM layout (each tile 128 rows x 128 bytes, 1024-aligned)
#define OFF_AH 0
#define OFF_AL 16384
#define OFF_BH 32768
#define OFF_BL 49152
#define STAGE_BYTES 65536
#define SMEM_CTRL 1024
#define SMEM_TOTAL (SMEM_CTRL + STAGES * STAGE_BYTES)   // 197632

// ---------------------------------------------------------------------------
// Scratch: fp16 hi/lo splits of A [B,M,K]; B transposed to [B,N,K] hi/lo
// ---------------------------------------------------------------------------
__device__ alignas(1024) __half g_Ah[(size_t)BATCH * MDIM * KDIM];
__device__ alignas(1024) __half g_Al[(size_t)BATCH * MDIM * KDIM];
__device__ alignas(1024) __half g_Bh[(size_t)BATCH * NDIM * KDIM];
__device__ alignas(1024) __half g_Bl[(size_t)BATCH * NDIM * KDIM];

// ---------------------------------------------------------------------------
// PTX helpers — sm_90-class only (NO 'a'-suffix features; target is sm_103)
// ---------------------------------------------------------------------------
__device__ __forceinline__ uint32_t smem_u32(const void* p) {
    uint32_t a;
    asm("{ .reg .u64 t; cvta.to.shared.u64 t, %1; cvt.u32.u64 %0, t; }"
        : "=r"(a) : "l"(p));
    return a;
}

#define MBARRIER_INIT(addr, cnt) \
    asm volatile("mbarrier.init.shared.b64 [%0], %1;" :: "r"(addr), "r"(cnt) : "memory")

#define MBARRIER_EXPECT_TX(addr, bytes) \
    asm volatile("mbarrier.arrive.expect_tx.shared.b64 _, [%0], %1;" \
                 :: "r"(addr), "r"(bytes) : "memory")

#define MBAR_WAIT(addr, parity) do {                                          \
    asm volatile(                                                             \
        "{\n\t.reg .pred P1;\n\t"                                             \
        "WAIT_LOOP_%=:\n\t"                                                   \
        "mbarrier.try_wait.parity.acquire.cta.shared::cta.b64 P1, [%0], %1, 0x989680;\n\t" \
        "@P1 bra.uni WAIT_DONE_%=;\n\t"                                       \
        "bra.uni WAIT_LOOP_%=;\n\t"                                           \
        "WAIT_DONE_%=:\n\t}"                                                  \
        :: "r"((uint32_t)(addr)), "r"((uint32_t)(parity)) : "memory");        \
} while (0)

__device__ __forceinline__ void tma2d(uint32_t smem_dst, const CUtensorMap* map,
                                      int x, int y, uint32_t mbar) {
    asm volatile(
        "cp.async.bulk.tensor.2d.shared::cta.global.tile.mbarrier::complete_tx::bytes "
        "[%0], [%1, {%2, %3}], [%4];"
        :: "r"(smem_dst), "l"(map), "r"(x), "r"(y), "r"(mbar)
        : "memory");
}

__device__ __forceinline__ void ldsm_x4(uint32_t* r, uint32_t addr) {
    asm volatile("ldmatrix.sync.aligned.m8n8.x4.shared.b16 {%0,%1,%2,%3}, [%4];"
                 : "=r"(r[0]), "=r"(r[1]), "=r"(r[2]), "=r"(r[3]) : "r"(addr));
}

// fp16 inputs, fp32 accumulate (main term)
__device__ __forceinline__ void mma_f32acc(float* d, const uint32_t* a,
                                           uint32_t b0, uint32_t b1) {
    asm volatile(
        "mma.sync.aligned.m16n8k16.row.col.f32.f16.f16.f32 "
        "{%0,%1,%2,%3}, {%4,%5,%6,%7}, {%8,%9}, {%0,%1,%2,%3};"
        : "+f"(d[0]), "+f"(d[1]), "+f"(d[2]), "+f"(d[3])
        : "r"(a[0]), "r"(a[1]), "r"(a[2]), "r"(a[3]), "r"(b0), "r"(b1));
}

// fp16 inputs, fp16 accumulate (cross terms — possibly 2x issue rate)
__device__ __forceinline__ void mma_f16acc(uint32_t* d, const uint32_t* a,
                                           uint32_t b0, uint32_t b1) {
    asm volatile(
        "mma.sync.aligned.m16n8k16.row.col.f16.f16.f16.f16 "
        "{%0,%1}, {%2,%3,%4,%5}, {%6,%7}, {%0,%1};"
        : "+r"(d[0]), "+r"(d[1])
        : "r"(a[0]), "r"(a[1]), "r"(a[2]), "r"(a[3]), "r"(b0), "r"(b1));
}

// ---------------------------------------------------------------------------
// Conversion kernels (fp16 hi/lo split)
// ---------------------------------------------------------------------------
__global__ void cvtA_kernel(const float* __restrict__ a) {
    const size_t n4 = (size_t)BATCH * MDIM * KDIM / 4;
    const float4* a4 = (const float4*)a;
    uint2* hi = (uint2*)g_Ah;
    uint2* lo = (uint2*)g_Al;
    for (size_t i = (size_t)blockIdx.x * blockDim.x + threadIdx.x; i < n4;
         i += (size_t)gridDim.x * blockDim.x) {
        float4 v = a4[i];
        __half h0 = __float2half_rn(v.x);
        __half h1 = __float2half_rn(v.y);
        __half h2 = __float2half_rn(v.z);
        __half h3 = __float2half_rn(v.w);
        __half l0 = __float2half_rn(v.x - __half2float(h0));
        __half l1 = __float2half_rn(v.y - __half2float(h1));
        __half l2 = __float2half_rn(v.z - __half2float(h2));
        __half l3 = __float2half_rn(v.w - __half2float(h3));
        uint2 hv, lv;
        hv.x = (uint32_t)__half_as_ushort(h0) | ((uint32_t)__half_as_ushort(h1) << 16);
        hv.y = (uint32_t)__half_as_ushort(h2) | ((uint32_t)__half_as_ushort(h3) << 16);
        lv.x = (uint32_t)__half_as_ushort(l0) | ((uint32_t)__half_as_ushort(l1) << 16);
        lv.y = (uint32_t)__half_as_ushort(l2) | ((uint32_t)__half_as_ushort(l3) << 16);
        hi[i] = hv;
        lo[i] = lv;
    }
}

// B[b][k][n] (n contiguous) -> Bt[b][n][k] (k contiguous), split hi/lo
__global__ void cvtB_kernel(const float* __restrict__ bsrc) {
    __shared__ float t[32][33];
    const int b = blockIdx.z;
    const int n0 = blockIdx.x * 32;
    const int k0 = blockIdx.y * 32;
    const int tx = threadIdx.x, ty = threadIdx.y;
    const float* src = bsrc + (size_t)b * KDIM * NDIM;
#pragma unroll
    for (int j = 0; j < 32; j += 8)
        t[ty + j][tx] = src[(size_t)(k0 + ty + j) * NDIM + n0 + tx];
    __syncthreads();
    const size_t base = (size_t)b * NDIM * KDIM;
#pragma unroll
    for (int j = 0; j < 32; j += 8) {
        float v = t[tx][ty + j];
        __half h = __float2half_rn(v);
        __half l = __float2half_rn(v - __half2float(h));
        size_t o = base + (size_t)(n0 + ty + j) * KDIM + (k0 + tx);
        g_Bh[o] = h;
        g_Bl[o] = l;
    }
}

// ---------------------------------------------------------------------------
// GEMM: 128x128 tile per CTA, fp16 2-digit 3-term, TMA(SW128)+ldmatrix+mma
// Main term f32-acc; cross terms f16-acc (testing 2x half-accumulate rate).
// 256 threads = 8 warps, warp grid 4(M) x 2(N), warp tile 32x64.
// ---------------------------------------------------------------------------
__global__ void __launch_bounds__(256, 1) gemm_kernel(
    const __grid_constant__ CUtensorMap mAh,
    const __grid_constant__ CUtensorMap mAl,
    const __grid_constant__ CUtensorMap mBh,
    const __grid_constant__ CUtensorMap mBl,
    float* __restrict__ C)
{
    extern __shared__ char smem[];
    const uint32_t sb = smem_u32(smem);
    const int tid = threadIdx.x;
    const int wid = tid >> 5;
    const int lane = tid & 31;
    const int warpM = wid & 3;        // 4 groups of 32 rows
    const int warpN = wid >> 2;       // 2 groups of 64 cols

    const int tn = blockIdx.x;
    const int tm = blockIdx.y;
    const int bb = blockIdx.z;

    if (tid == 0) {
#pragma unroll
        for (int s = 0; s < STAGES; s++) MBARRIER_INIT(sb + 8 * s, 1);
        asm volatile("fence.proxy.async.shared::cta;" ::: "memory");
    }
    __syncthreads();

    const int rowA = bb * MDIM + tm * TILE_M;
    const int rowB = bb * NDIM + tn * TILE_N;

    // Prologue: fill all stages
    if (tid == 0) {
#pragma unroll
        for (int s = 0; s < STAGES; s++) {
            uint32_t st = sb + SMEM_CTRL + s * STAGE_BYTES;
            MBARRIER_EXPECT_TX(sb + 8 * s, (uint32_t)STAGE_BYTES);
            tma2d(st + OFF_AH, &mAh, s * KC, rowA, sb + 8 * s);
            tma2d(st + OFF_AL, &mAl, s * KC, rowA, sb + 8 * s);
            tma2d(st + OFF_BH, &mBh, s * KC, rowB, sb + 8 * s);
            tma2d(st + OFF_BL, &mBl, s * KC, rowB, sb + 8 * s);
        }
    }

    // ldmatrix addressing (SW128 swizzle = XOR bits[6:4] with row&7)
    const int r15 = lane & 15;
    const int kh = lane >> 4;                 // which 8-k half
    const uint32_t xorv = (uint32_t)((lane & 7) << 4);
    uint32_t kpart[4];
#pragma unroll
    for (int ks = 0; ks < 4; ks++)
        kpart[ks] = ((uint32_t)(ks * 32 + kh * 16)) ^ xorv;

    // Tile-local row byte bases
    uint32_t aRowOff[2], bRowOff[4];
#pragma unroll
    for (int mt = 0; mt < 2; mt++)
        aRowOff[mt] = (uint32_t)(warpM * 32 + mt * 16 + r15) * 128;
#pragma unroll
    for (int ng = 0; ng < 4; ng++)
        bRowOff[ng] = (uint32_t)(warpN * 64 + ng * 16 + r15) * 128;

    float acc[2][8][4];
    uint32_t accX[2][8][2];            // fp16x2 cross-term accumulators
#pragma unroll
    for (int mt = 0; mt < 2; mt++)
#pragma unroll
        for (int nt = 0; nt < 8; nt++) {
#pragma unroll
            for (int i = 0; i < 4; i++) acc[mt][nt][i] = 0.0f;
            accX[mt][nt][0] = 0u;
            accX[mt][nt][1] = 0u;
        }

    int pf[STAGES] = {0, 0, 0};

    for (int c = 0; c < NCHUNK; c++) {
        const int s = c % STAGES;
        MBAR_WAIT(sb + 8 * s, pf[s]);
        pf[s] ^= 1;
        const uint32_t st = sb + SMEM_CTRL + s * STAGE_BYTES;

#pragma unroll
        for (int ks = 0; ks < 4; ks++) {
            uint32_t ah[2][4], al[2][4], bh[4][4], bl[4][4];
#pragma unroll
            for (int mt = 0; mt < 2; mt++) {
                ldsm_x4(ah[mt], st + OFF_AH + aRowOff[mt] + kpart[ks]);
                ldsm_x4(al[mt], st + OFF_AL + aRowOff[mt] + kpart[ks]);
            }
#pragma unroll
            for (int ng = 0; ng < 4; ng++) {
                ldsm_x4(bh[ng], st + OFF_BH + bRowOff[ng] + kpart[ks]);
                ldsm_x4(bl[ng], st + OFF_BL + bRowOff[ng] + kpart[ks]);
            }
#pragma unroll
            for (int mt = 0; mt < 2; mt++) {
#pragma unroll
                for (int nt = 0; nt < 8; nt++) {
                    const int ng = nt >> 1;
                    const int o = nt & 1;
                    mma_f32acc(acc[mt][nt], ah[mt], bh[ng][o], bh[ng][o + 2]);
                    mma_f16acc(accX[mt][nt], al[mt], bh[ng][o], bh[ng][o + 2]);
                    mma_f16acc(accX[mt][nt], ah[mt], bl[ng][o], bl[ng][o + 2]);
                }
            }
        }

        __syncthreads();   // all warps done reading stage s
        if (tid == 0 && c + STAGES < NCHUNK) {
            const int kk = (c + STAGES) * KC;
            MBARRIER_EXPECT_TX(sb + 8 * s, (uint32_t)STAGE_BYTES);
            tma2d(st + OFF_AH, &mAh, kk, rowA, sb + 8 * s);
            tma2d(st + OFF_AL, &mAl, kk, rowA, sb + 8 * s);
            tma2d(st + OFF_BH, &mBh, kk, rowB, sb + 8 * s);
            tma2d(st + OFF_BL, &mBl, kk, rowB, sb + 8 * s);
        }
    }

    // Epilogue: C = acc + float(accX). accX reg j holds halves (c2j, c2j+1).
    const int cRow0 = tm * TILE_M + warpM * 32 + (lane >> 2);
    const int cCol0 = tn * TILE_N + warpN * 64 + (lane & 3) * 2;
    float* Cb = C + (size_t)bb * MDIM * NDIM;
#pragma unroll
    for (int mt = 0; mt < 2; mt++) {
        const int r0 = cRow0 + mt * 16;
        float* rp0 = Cb + (size_t)r0 * NDIM + cCol0;
        float* rp1 = Cb + (size_t)(r0 + 8) * NDIM + cCol0;
#pragma unroll
        for (int nt = 0; nt < 8; nt++) {
            float2 x0 = __half22float2(*reinterpret_cast<__half2*>(&accX[mt][nt][0]));
            float2 x1 = __half22float2(*reinterpret_cast<__half2*>(&accX[mt][nt][1]));
            *reinterpret_cast<float2*>(rp0 + nt * 8) =
                make_float2(acc[mt][nt][0] + x0.x, acc[mt][nt][1] + x0.y);
            *reinterpret_cast<float2*>(rp1 + nt * 8) =
                make_float2(acc[mt][nt][2] + x1.x, acc[mt][nt][3] + x1.y);
        }
    }
}

// ---------------------------------------------------------------------------
// Host launch
// ---------------------------------------------------------------------------
typedef CUresult (*PFN_tmap_encode)(
    CUtensorMap*, CUtensorMapDataType, cuuint32_t, void*,
    const cuuint64_t*, const cuuint64_t*, const cuuint32_t*, const cuuint32_t*,
    CUtensorMapInterleave, CUtensorMapSwizzle, CUtensorMapL2promotion,
    CUtensorMapFloatOOBfill);

static void make_map_f16(PFN_tmap_encode enc, CUtensorMap* m, void* base,
                         cuuint64_t dim0, cuuint64_t dim1,
                         cuuint32_t box0, cuuint32_t box1) {
    cuuint64_t gd[2] = {dim0, dim1};
    cuuint64_t gs[1] = {dim0 * sizeof(__half)};
    cuuint32_t bd[2] = {box0, box1};
    cuuint32_t es[2] = {1, 1};
    enc(m, CU_TENSOR_MAP_DATA_TYPE_FLOAT16, 2, base, gd, gs, bd, es,
        CU_TENSOR_MAP_INTERLEAVE_NONE, CU_TENSOR_MAP_SWIZZLE_128B,
        CU_TENSOR_MAP_L2_PROMOTION_L2_128B, CU_TENSOR_MAP_FLOAT_OOB_FILL_NONE);
}

extern "C" void kernel_launch(void* const* d_in, const int* in_sizes, int n_in,
                              void* d_out, int out_size) {
    (void)in_sizes; (void)n_in; (void)out_size;
    const float* A = (const float*)d_in[0];
    const float* B = (const float*)d_in[1];
    float* C = (float*)d_out;

    cvtA_kernel<<<2048, 256>>>(A);
    cvtB_kernel<<<dim3(NDIM / 32, KDIM / 32, BATCH), dim3(32, 8)>>>(B);

    void *pAh = nullptr, *pAl = nullptr, *pBh = nullptr, *pBl = nullptr;
    cudaGetSymbolAddress(&pAh, g_Ah);
    cudaGetSymbolAddress(&pAl, g_Al);
    cudaGetSymbolAddress(&pBh, g_Bh);
    cudaGetSymbolAddress(&pBl, g_Bl);

    void* fn = nullptr;
    cudaDriverEntryPointQueryResult qr;
    cudaGetDriverEntryPoint("cuTensorMapEncodeTiled", &fn, cudaEnableDefault, &qr);
    if (!fn) return;
    PFN_tmap_encode enc = (PFN_tmap_encode)fn;

    CUtensorMap mAh, mAl, mBh, mBl;
    make_map_f16(enc, &mAh, pAh, KDIM, (cuuint64_t)BATCH * MDIM, KC, TILE_M);
    make_map_f16(enc, &mAl, pAl, KDIM, (cuuint64_t)BATCH * MDIM, KC, TILE_M);
    make_map_f16(enc, &mBh, pBh, KDIM, (cuuint64_t)BATCH * NDIM, KC, TILE_N);
    make_map_f16(enc, &mBl, pBl, KDIM, (cuuint64_t)BATCH * NDIM, KC, TILE_N);

    cudaFuncSetAttribute(gemm_kernel, cudaFuncAttributeMaxDynamicSharedMemorySize,
                         SMEM_TOTAL);
    gemm_kernel<<<dim3(NDIM / TILE_N, MDIM / TILE_M, BATCH), 256, SMEM_TOTAL>>>(
        mAh, mAl, mBh, mBl, C);
}

// round 7
// speedup vs baseline: 6.2329x; 2.1643x over previous
#include <cuda_runtime.h>
#include <cuda.h>
#include <cuda_fp16.h>
#include <cstdint>
#include <cstddef>

// Problem dims (fixed by the dataset)
#define BATCH 4
#define MDIM 2048
#define NDIM 2048
#define KDIM 2048

// GEMM tiling
#define TILE_M 128
#define TILE_N 128
#define KC 64                    // K per chunk: 64 fp16 = 128B row = SW128 atom
#define NCHUNK (KDIM / KC)       // 32
#define STAGES 4

// Per-stage SMEM layout (A tile 16KB + B tile 16KB, 1024-aligned)
#define OFF_AH 0
#define OFF_BH 16384
#define STAGE_BYTES 32768
#define SMEM_CTRL 1024
#define SMEM_TOTAL (SMEM_CTRL + STAGES * STAGE_BYTES)   // 132096

// ---------------------------------------------------------------------------
// Scratch: fp16 of A [B,M,K]; B transposed to [B,N,K] (K-major)
// ---------------------------------------------------------------------------
__device__ alignas(1024) __half g_Ah[(size_t)BATCH * MDIM * KDIM];
__device__ alignas(1024) __half g_Bh[(size_t)BATCH * NDIM * KDIM];

// ---------------------------------------------------------------------------
// PTX helpers — sm_90-class only (NO 'a'-suffix features; target is sm_103)
// ---------------------------------------------------------------------------
__device__ __forceinline__ uint32_t smem_u32(const void* p) {
    uint32_t a;
    asm("{ .reg .u64 t; cvta.to.shared.u64 t, %1; cvt.u32.u64 %0, t; }"
        : "=r"(a) : "l"(p));
    return a;
}

#define MBARRIER_INIT(addr, cnt) \
    asm volatile("mbarrier.init.shared.b64 [%0], %1;" :: "r"(addr), "r"(cnt) : "memory")

#define MBARRIER_EXPECT_TX(addr, bytes) \
    asm volatile("mbarrier.arrive.expect_tx.shared.b64 _, [%0], %1;" \
                 :: "r"(addr), "r"(bytes) : "memory")

#define MBAR_WAIT(addr, parity) do {                                          \
    asm volatile(                                                             \
        "{\n\t.reg .pred P1;\n\t"                                             \
        "WAIT_LOOP_%=:\n\t"                                                   \
        "mbarrier.try_wait.parity.acquire.cta.shared::cta.b64 P1, [%0], %1, 0x989680;\n\t" \
        "@P1 bra.uni WAIT_DONE_%=;\n\t"                                       \
        "bra.uni WAIT_LOOP_%=;\n\t"                                           \
        "WAIT_DONE_%=:\n\t}"                                                  \
        :: "r"((uint32_t)(addr)), "r"((uint32_t)(parity)) : "memory");        \
} while (0)

__device__ __forceinline__ void tma2d(uint32_t smem_dst, const CUtensorMap* map,
                                      int x, int y, uint32_t mbar) {
    asm volatile(
        "cp.async.bulk.tensor.2d.shared::cta.global.tile.mbarrier::complete_tx::bytes "
        "[%0], [%1, {%2, %3}], [%4];"
        :: "r"(smem_dst), "l"(map), "r"(x), "r"(y), "r"(mbar)
        : "memory");
}

__device__ __forceinline__ void ldsm_x4(uint32_t* r, uint32_t addr) {
    asm volatile("ldmatrix.sync.aligned.m8n8.x4.shared.b16 {%0,%1,%2,%3}, [%4];"
                 : "=r"(r[0]), "=r"(r[1]), "=r"(r[2]), "=r"(r[3]) : "r"(addr));
}

// fp16 inputs, fp32 accumulate
__device__ __forceinline__ void mma_f32acc(float* d, const uint32_t* a,
                                           uint32_t b0, uint32_t b1) {
    asm volatile(
        "mma.sync.aligned.m16n8k16.row.col.f32.f16.f16.f32 "
        "{%0,%1,%2,%3}, {%4,%5,%6,%7}, {%8,%9}, {%0,%1,%2,%3};"
        : "+f"(d[0]), "+f"(d[1]), "+f"(d[2]), "+f"(d[3])
        : "r"(a[0]), "r"(a[1]), "r"(a[2]), "r"(a[3]), "r"(b0), "r"(b1));
}

// ---------------------------------------------------------------------------
// Conversion kernels (fp16 round-to-nearest)
// ---------------------------------------------------------------------------
__global__ void cvtA_kernel(const float* __restrict__ a) {
    const size_t n4 = (size_t)BATCH * MDIM * KDIM / 4;
    const float4* a4 = (const float4*)a;
    uint2* hi = (uint2*)g_Ah;
    for (size_t i = (size_t)blockIdx.x * blockDim.x + threadIdx.x; i < n4;
         i += (size_t)gridDim.x * blockDim.x) {
        float4 v = a4[i];
        __half h0 = __float2half_rn(v.x);
        __half h1 = __float2half_rn(v.y);
        __half h2 = __float2half_rn(v.z);
        __half h3 = __float2half_rn(v.w);
        uint2 hv;
        hv.x = (uint32_t)__half_as_ushort(h0) | ((uint32_t)__half_as_ushort(h1) << 16);
        hv.y = (uint32_t)__half_as_ushort(h2) | ((uint32_t)__half_as_ushort(h3) << 16);
        hi[i] = hv;
    }
}

// B[b][k][n] (n contiguous) -> Bt[b][n][k] (k contiguous)
__global__ void cvtB_kernel(const float* __restrict__ bsrc) {
    __shared__ float t[32][33];
    const int b = blockIdx.z;
    const int n0 = blockIdx.x * 32;
    const int k0 = blockIdx.y * 32;
    const int tx = threadIdx.x, ty = threadIdx.y;
    const float* src = bsrc + (size_t)b * KDIM * NDIM;
#pragma unroll
    for (int j = 0; j < 32; j += 8)
        t[ty + j][tx] = src[(size_t)(k0 + ty + j) * NDIM + n0 + tx];
    __syncthreads();
    const size_t base = (size_t)b * NDIM * KDIM;
#pragma unroll
    for (int j = 0; j < 32; j += 8) {
        size_t o = base + (size_t)(n0 + ty + j) * KDIM + (k0 + tx);
        g_Bh[o] = __float2half_rn(t[tx][ty + j]);
    }
}

// ---------------------------------------------------------------------------
// GEMM: 128x128 tile per CTA, fp16 single-term, TMA(SW128)+ldmatrix+mma
// 256 threads = 8 warps, warp grid 4(M) x 2(N), warp tile 32x64.
// ---------------------------------------------------------------------------
__global__ void __launch_bounds__(256, 1) gemm_kernel(
    const __grid_constant__ CUtensorMap mAh,
    const __grid_constant__ CUtensorMap mBh,
    float* __restrict__ C)
{
    extern __shared__ char smem[];
    const uint32_t sb = smem_u32(smem);
    const int tid = threadIdx.x;
    const int wid = tid >> 5;
    const int lane = tid & 31;
    const int warpM = wid & 3;        // 4 groups of 32 rows
    const int warpN = wid >> 2;       // 2 groups of 64 cols

    const int tn = blockIdx.x;
    const int tm = blockIdx.y;
    const int bb = blockIdx.z;

    if (tid == 0) {
#pragma unroll
        for (int s = 0; s < STAGES; s++) MBARRIER_INIT(sb + 8 * s, 1);
        asm volatile("fence.proxy.async.shared::cta;" ::: "memory");
    }
    __syncthreads();

    const int rowA = bb * MDIM + tm * TILE_M;
    const int rowB = bb * NDIM + tn * TILE_N;

    // Prologue: fill all stages
    if (tid == 0) {
#pragma unroll
        for (int s = 0; s < STAGES; s++) {
            uint32_t st = sb + SMEM_CTRL + s * STAGE_BYTES;
            MBARRIER_EXPECT_TX(sb + 8 * s, (uint32_t)STAGE_BYTES);
            tma2d(st + OFF_AH, &mAh, s * KC, rowA, sb + 8 * s);
            tma2d(st + OFF_BH, &mBh, s * KC, rowB, sb + 8 * s);
        }
    }

    // ldmatrix addressing (SW128 swizzle = XOR bits[6:4] with row&7)
    const int r15 = lane & 15;
    const int kh = lane >> 4;                 // which 8-k half
    const uint32_t xorv = (uint32_t)((lane & 7) << 4);
    uint32_t kpart[4];
#pragma unroll
    for (int ks = 0; ks < 4; ks++)
        kpart[ks] = ((uint32_t)(ks * 32 + kh * 16)) ^ xorv;

    // Tile-local row byte bases
    uint32_t aRowOff[2], bRowOff[4];
#pragma unroll
    for (int mt = 0; mt < 2; mt++)
        aRowOff[mt] = (uint32_t)(warpM * 32 + mt * 16 + r15) * 128;
#pragma unroll
    for (int ng = 0; ng < 4; ng++)
        bRowOff[ng] = (uint32_t)(warpN * 64 + ng * 16 + r15) * 128;

    float acc[2][8][4];
#pragma unroll
    for (int mt = 0; mt < 2; mt++)
#pragma unroll
        for (int nt = 0; nt < 8; nt++)
#pragma unroll
            for (int i = 0; i < 4; i++) acc[mt][nt][i] = 0.0f;

    int pf[STAGES] = {0, 0, 0, 0};

    for (int c = 0; c < NCHUNK; c++) {
        const int s = c % STAGES;
        MBAR_WAIT(sb + 8 * s, pf[s]);
        pf[s] ^= 1;
        const uint32_t st = sb + SMEM_CTRL + s * STAGE_BYTES;

#pragma unroll
        for (int ks = 0; ks < 4; ks++) {
            uint32_t ah[2][4], bh[4][4];
#pragma unroll
            for (int mt = 0; mt < 2; mt++)
                ldsm_x4(ah[mt], st + OFF_AH + aRowOff[mt] + kpart[ks]);
#pragma unroll
            for (int ng = 0; ng < 4; ng++)
                ldsm_x4(bh[ng], st + OFF_BH + bRowOff[ng] + kpart[ks]);
#pragma unroll
            for (int mt = 0; mt < 2; mt++) {
#pragma unroll
                for (int nt = 0; nt < 8; nt++) {
                    const int ng = nt >> 1;
                    const int o = nt & 1;
                    mma_f32acc(acc[mt][nt], ah[mt], bh[ng][o], bh[ng][o + 2]);
                }
            }
        }

        __syncthreads();   // all warps done reading stage s
        if (tid == 0 && c + STAGES < NCHUNK) {
            const int kk = (c + STAGES) * KC;
            MBARRIER_EXPECT_TX(sb + 8 * s, (uint32_t)STAGE_BYTES);
            tma2d(st + OFF_AH, &mAh, kk, rowA, sb + 8 * s);
            tma2d(st + OFF_BH, &mBh, kk, rowB, sb + 8 * s);
        }
    }

    // Epilogue: d frag: c0,c1 -> row lane/4, cols 2(lane%4)+{0,1}; c2,c3 -> row+8
    const int cRow0 = tm * TILE_M + warpM * 32 + (lane >> 2);
    const int cCol0 = tn * TILE_N + warpN * 64 + (lane & 3) * 2;
    float* Cb = C + (size_t)bb * MDIM * NDIM;
#pragma unroll
    for (int mt = 0; mt < 2; mt++) {
        const int r0 = cRow0 + mt * 16;
        float* rp0 = Cb + (size_t)r0 * NDIM + cCol0;
        float* rp1 = Cb + (size_t)(r0 + 8) * NDIM + cCol0;
#pragma unroll
        for (int nt = 0; nt < 8; nt++) {
            *reinterpret_cast<float2*>(rp0 + nt * 8) =
                make_float2(acc[mt][nt][0], acc[mt][nt][1]);
            *reinterpret_cast<float2*>(rp1 + nt * 8) =
                make_float2(acc[mt][nt][2], acc[mt][nt][3]);
        }
    }
}

// ---------------------------------------------------------------------------
// Host launch
// ---------------------------------------------------------------------------
typedef CUresult (*PFN_tmap_encode)(
    CUtensorMap*, CUtensorMapDataType, cuuint32_t, void*,
    const cuuint64_t*, const cuuint64_t*, const cuuint32_t*, const cuuint32_t*,
    CUtensorMapInterleave, CUtensorMapSwizzle, CUtensorMapL2promotion,
    CUtensorMapFloatOOBfill);

static void make_map_f16(PFN_tmap_encode enc, CUtensorMap* m, void* base,
                         cuuint64_t dim0, cuuint64_t dim1,
                         cuuint32_t box0, cuuint32_t box1) {
    cuuint64_t gd[2] = {dim0, dim1};
    cuuint64_t gs[1] = {dim0 * sizeof(__half)};
    cuuint32_t bd[2] = {box0, box1};
    cuuint32_t es[2] = {1, 1};
    enc(m, CU_TENSOR_MAP_DATA_TYPE_FLOAT16, 2, base, gd, gs, bd, es,
        CU_TENSOR_MAP_INTERLEAVE_NONE, CU_TENSOR_MAP_SWIZZLE_128B,
        CU_TENSOR_MAP_L2_PROMOTION_L2_128B, CU_TENSOR_MAP_FLOAT_OOB_FILL_NONE);
}

extern "C" void kernel_launch(void* const* d_in, const int* in_sizes, int n_in,
                              void* d_out, int out_size) {
    (void)in_sizes; (void)n_in; (void)out_size;
    const float* A = (const float*)d_in[0];
    const float* B = (const float*)d_in[1];
    float* C = (float*)d_out;

    cvtA_kernel<<<2048, 256>>>(A);
    cvtB_kernel<<<dim3(NDIM / 32, KDIM / 32, BATCH), dim3(32, 8)>>>(B);

    void *pAh = nullptr, *pBh = nullptr;
    cudaGetSymbolAddress(&pAh, g_Ah);
    cudaGetSymbolAddress(&pBh, g_Bh);

    void* fn = nullptr;
    cudaDriverEntryPointQueryResult qr;
    cudaGetDriverEntryPoint("cuTensorMapEncodeTiled", &fn, cudaEnableDefault, &qr);
    if (!fn) return;
    PFN_tmap_encode enc = (PFN_tmap_encode)fn;

    CUtensorMap mAh, mBh;
    make_map_f16(enc, &mAh, pAh, KDIM, (cuuint64_t)BATCH * MDIM, KC, TILE_M);
    make_map_f16(enc, &mBh, pBh, KDIM, (cuuint64_t)BATCH * NDIM, KC, TILE_N);

    cudaFuncSetAttribute(gemm_kernel, cudaFuncAttributeMaxDynamicSharedMemorySize,
                         SMEM_TOTAL);
    gemm_kernel<<<dim3(NDIM / TILE_N, MDIM / TILE_M, BATCH), 256, SMEM_TOTAL>>>(
        mAh, mBh, C);
}

// round 8
// speedup vs baseline: 6.4296x; 1.0316x over previous
#include <cuda_runtime.h>
#include <cuda.h>
#include <cuda_fp16.h>
#include <cstdint>
#include <cstddef>

// Problem dims (fixed by the dataset)
#define BATCH 4
#define MDIM 2048
#define NDIM 2048
#define KDIM 2048

// GEMM tiling: 128x64 tile, 2 CTAs per SM to hide per-chunk overhead
#define TILE_M 128
#define TILE_N 64
#define KC 64                    // K per chunk: 64 fp16 = 128B row = SW128 atom
#define NCHUNK (KDIM / KC)       // 32
#define STAGES 4

// Per-stage SMEM layout (A tile 16KB + B tile 8KB, 1024-aligned)
#define OFF_AH 0
#define OFF_BH 16384
#define STAGE_BYTES 24576
#define SMEM_CTRL 1024
#define SMEM_TOTAL (SMEM_CTRL + STAGES * STAGE_BYTES)   // 99328 (x2 CTAs = 198656/SM)

// ---------------------------------------------------------------------------
// Scratch: fp16 of A [B,M,K]; B transposed to [B,N,K] (K-major)
// ---------------------------------------------------------------------------
__device__ alignas(1024) __half g_Ah[(size_t)BATCH * MDIM * KDIM];
__device__ alignas(1024) __half g_Bh[(size_t)BATCH * NDIM * KDIM];

// ---------------------------------------------------------------------------
// PTX helpers — sm_90-class only (NO 'a'-suffix features; target is sm_103)
// ---------------------------------------------------------------------------
__device__ __forceinline__ uint32_t smem_u32(const void* p) {
    uint32_t a;
    asm("{ .reg .u64 t; cvta.to.shared.u64 t, %1; cvt.u32.u64 %0, t; }"
        : "=r"(a) : "l"(p));
    return a;
}

#define MBARRIER_INIT(addr, cnt) \
    asm volatile("mbarrier.init.shared.b64 [%0], %1;" :: "r"(addr), "r"(cnt) : "memory")

#define MBARRIER_EXPECT_TX(addr, bytes) \
    asm volatile("mbarrier.arrive.expect_tx.shared.b64 _, [%0], %1;" \
                 :: "r"(addr), "r"(bytes) : "memory")

#define MBAR_WAIT(addr, parity) do {                                          \
    asm volatile(                                                             \
        "{\n\t.reg .pred P1;\n\t"                                             \
        "WAIT_LOOP_%=:\n\t"                                                   \
        "mbarrier.try_wait.parity.acquire.cta.shared::cta.b64 P1, [%0], %1, 0x989680;\n\t" \
        "@P1 bra.uni WAIT_DONE_%=;\n\t"                                       \
        "bra.uni WAIT_LOOP_%=;\n\t"                                           \
        "WAIT_DONE_%=:\n\t}"                                                  \
        :: "r"((uint32_t)(addr)), "r"((uint32_t)(parity)) : "memory");        \
} while (0)

__device__ __forceinline__ void tma2d(uint32_t smem_dst, const CUtensorMap* map,
                                      int x, int y, uint32_t mbar) {
    asm volatile(
        "cp.async.bulk.tensor.2d.shared::cta.global.tile.mbarrier::complete_tx::bytes "
        "[%0], [%1, {%2, %3}], [%4];"
        :: "r"(smem_dst), "l"(map), "r"(x), "r"(y), "r"(mbar)
        : "memory");
}

__device__ __forceinline__ void ldsm_x4(uint32_t* r, uint32_t addr) {
    asm volatile("ldmatrix.sync.aligned.m8n8.x4.shared.b16 {%0,%1,%2,%3}, [%4];"
                 : "=r"(r[0]), "=r"(r[1]), "=r"(r[2]), "=r"(r[3]) : "r"(addr));
}

// fp16 inputs, fp32 accumulate
__device__ __forceinline__ void mma_f32acc(float* d, const uint32_t* a,
                                           uint32_t b0, uint32_t b1) {
    asm volatile(
        "mma.sync.aligned.m16n8k16.row.col.f32.f16.f16.f32 "
        "{%0,%1,%2,%3}, {%4,%5,%6,%7}, {%8,%9}, {%0,%1,%2,%3};"
        : "+f"(d[0]), "+f"(d[1]), "+f"(d[2]), "+f"(d[3])
        : "r"(a[0]), "r"(a[1]), "r"(a[2]), "r"(a[3]), "r"(b0), "r"(b1));
}

// ---------------------------------------------------------------------------
// Conversion kernels (fp16 round-to-nearest)
// ---------------------------------------------------------------------------
__global__ void cvtA_kernel(const float* __restrict__ a) {
    const size_t n4 = (size_t)BATCH * MDIM * KDIM / 4;
    const float4* a4 = (const float4*)a;
    uint2* hi = (uint2*)g_Ah;
    for (size_t i = (size_t)blockIdx.x * blockDim.x + threadIdx.x; i < n4;
         i += (size_t)gridDim.x * blockDim.x) {
        float4 v = a4[i];
        __half h0 = __float2half_rn(v.x);
        __half h1 = __float2half_rn(v.y);
        __half h2 = __float2half_rn(v.z);
        __half h3 = __float2half_rn(v.w);
        uint2 hv;
        hv.x = (uint32_t)__half_as_ushort(h0) | ((uint32_t)__half_as_ushort(h1) << 16);
        hv.y = (uint32_t)__half_as_ushort(h2) | ((uint32_t)__half_as_ushort(h3) << 16);
        hi[i] = hv;
    }
}

// B[b][k][n] (n contiguous) -> Bt[b][n][k] (k contiguous)
__global__ void cvtB_kernel(const float* __restrict__ bsrc) {
    __shared__ float t[32][33];
    const int b = blockIdx.z;
    const int n0 = blockIdx.x * 32;
    const int k0 = blockIdx.y * 32;
    const int tx = threadIdx.x, ty = threadIdx.y;
    const float* src = bsrc + (size_t)b * KDIM * NDIM;
#pragma unroll
    for (int j = 0; j < 32; j += 8)
        t[ty + j][tx] = src[(size_t)(k0 + ty + j) * NDIM + n0 + tx];
    __syncthreads();
    const size_t base = (size_t)b * NDIM * KDIM;
#pragma unroll
    for (int j = 0; j < 32; j += 8) {
        size_t o = base + (size_t)(n0 + ty + j) * KDIM + (k0 + tx);
        g_Bh[o] = __float2half_rn(t[tx][ty + j]);
    }
}

// ---------------------------------------------------------------------------
// GEMM: 128x64 tile per CTA (2 CTAs/SM), fp16, TMA(SW128)+ldmatrix+mma
// 256 threads = 8 warps, warp grid 4(M) x 2(N), warp tile 32x32.
// ---------------------------------------------------------------------------
__global__ void __launch_bounds__(256, 2) gemm_kernel(
    const __grid_constant__ CUtensorMap mAh,
    const __grid_constant__ CUtensorMap mBh,
    float* __restrict__ C)
{
    extern __shared__ char smem[];
    const uint32_t sb = smem_u32(smem);
    const int tid = threadIdx.x;
    const int wid = tid >> 5;
    const int lane = tid & 31;
    const int warpM = wid & 3;        // 4 groups of 32 rows
    const int warpN = wid >> 2;       // 2 groups of 32 cols

    const int tn = blockIdx.x;
    const int tm = blockIdx.y;
    const int bb = blockIdx.z;

    if (tid == 0) {
#pragma unroll
        for (int s = 0; s < STAGES; s++) MBARRIER_INIT(sb + 8 * s, 1);
        asm volatile("fence.proxy.async.shared::cta;" ::: "memory");
    }
    __syncthreads();

    const int rowA = bb * MDIM + tm * TILE_M;
    const int rowB = bb * NDIM + tn * TILE_N;

    // Prologue: fill all stages
    if (tid == 0) {
#pragma unroll
        for (int s = 0; s < STAGES; s++) {
            uint32_t st = sb + SMEM_CTRL + s * STAGE_BYTES;
            MBARRIER_EXPECT_TX(sb + 8 * s, (uint32_t)STAGE_BYTES);
            tma2d(st + OFF_AH, &mAh, s * KC, rowA, sb + 8 * s);
            tma2d(st + OFF_BH, &mBh, s * KC, rowB, sb + 8 * s);
        }
    }

    // ldmatrix addressing (SW128 swizzle = XOR bits[6:4] with row&7)
    const int r15 = lane & 15;
    const int kh = lane >> 4;                 // which 8-k half
    const uint32_t xorv = (uint32_t)((lane & 7) << 4);
    uint32_t kpart[4];
#pragma unroll
    for (int ks = 0; ks < 4; ks++)
        kpart[ks] = ((uint32_t)(ks * 32 + kh * 16)) ^ xorv;

    // Tile-local row byte bases
    uint32_t aRowOff[2], bRowOff[2];
#pragma unroll
    for (int mt = 0; mt < 2; mt++)
        aRowOff[mt] = (uint32_t)(warpM * 32 + mt * 16 + r15) * 128;
#pragma unroll
    for (int ng = 0; ng < 2; ng++)
        bRowOff[ng] = (uint32_t)(warpN * 32 + ng * 16 + r15) * 128;

    float acc[2][4][4];
#pragma unroll
    for (int mt = 0; mt < 2; mt++)
#pragma unroll
        for (int nt = 0; nt < 4; nt++)
#pragma unroll
            for (int i = 0; i < 4; i++) acc[mt][nt][i] = 0.0f;

    int pf[STAGES] = {0, 0, 0, 0};

    for (int c = 0; c < NCHUNK; c++) {
        const int s = c % STAGES;
        MBAR_WAIT(sb + 8 * s, pf[s]);
        pf[s] ^= 1;
        const uint32_t st = sb + SMEM_CTRL + s * STAGE_BYTES;

#pragma unroll
        for (int ks = 0; ks < 4; ks++) {
            uint32_t ah[2][4], bh[2][4];
#pragma unroll
            for (int mt = 0; mt < 2; mt++)
                ldsm_x4(ah[mt], st + OFF_AH + aRowOff[mt] + kpart[ks]);
#pragma unroll
            for (int ng = 0; ng < 2; ng++)
                ldsm_x4(bh[ng], st + OFF_BH + bRowOff[ng] + kpart[ks]);
#pragma unroll
            for (int mt = 0; mt < 2; mt++) {
#pragma unroll
                for (int nt = 0; nt < 4; nt++) {
                    const int ng = nt >> 1;
                    const int o = nt & 1;
                    mma_f32acc(acc[mt][nt], ah[mt], bh[ng][o], bh[ng][o + 2]);
                }
            }
        }

        __syncthreads();   // all warps done reading stage s
        if (tid == 0 && c + STAGES < NCHUNK) {
            const int kk = (c + STAGES) * KC;
            MBARRIER_EXPECT_TX(sb + 8 * s, (uint32_t)STAGE_BYTES);
            tma2d(st + OFF_AH, &mAh, kk, rowA, sb + 8 * s);
            tma2d(st + OFF_BH, &mBh, kk, rowB, sb + 8 * s);
        }
    }

    // Epilogue: d frag: c0,c1 -> row lane/4, cols 2(lane%4)+{0,1}; c2,c3 -> row+8
    const int cRow0 = tm * TILE_M + warpM * 32 + (lane >> 2);
    const int cCol0 = tn * TILE_N + warpN * 32 + (lane & 3) * 2;
    float* Cb = C + (size_t)bb * MDIM * NDIM;
#pragma unroll
    for (int mt = 0; mt < 2; mt++) {
        const int r0 = cRow0 + mt * 16;
        float* rp0 = Cb + (size_t)r0 * NDIM + cCol0;
        float* rp1 = Cb + (size_t)(r0 + 8) * NDIM + cCol0;
#pragma unroll
        for (int nt = 0; nt < 4; nt++) {
            *reinterpret_cast<float2*>(rp0 + nt * 8) =
                make_float2(acc[mt][nt][0], acc[mt][nt][1]);
            *reinterpret_cast<float2*>(rp1 + nt * 8) =
                make_float2(acc[mt][nt][2], acc[mt][nt][3]);
        }
    }
}

// ---------------------------------------------------------------------------
// Host launch
// ---------------------------------------------------------------------------
typedef CUresult (*PFN_tmap_encode)(
    CUtensorMap*, CUtensorMapDataType, cuuint32_t, void*,
    const cuuint64_t*, const cuuint64_t*, const cuuint32_t*, const cuuint32_t*,
    CUtensorMapInterleave, CUtensorMapSwizzle, CUtensorMapL2promotion,
    CUtensorMapFloatOOBfill);

static void make_map_f16(PFN_tmap_encode enc, CUtensorMap* m, void* base,
                         cuuint64_t dim0, cuuint64_t dim1,
                         cuuint32_t box0, cuuint32_t box1) {
    cuuint64_t gd[2] = {dim0, dim1};
    cuuint64_t gs[1] = {dim0 * sizeof(__half)};
    cuuint32_t bd[2] = {box0, box1};
    cuuint32_t es[2] = {1, 1};
    enc(m, CU_TENSOR_MAP_DATA_TYPE_FLOAT16, 2, base, gd, gs, bd, es,
        CU_TENSOR_MAP_INTERLEAVE_NONE, CU_TENSOR_MAP_SWIZZLE_128B,
        CU_TENSOR_MAP_L2_PROMOTION_L2_128B, CU_TENSOR_MAP_FLOAT_OOB_FILL_NONE);
}

extern "C" void kernel_launch(void* const* d_in, const int* in_sizes, int n_in,
                              void* d_out, int out_size) {
    (void)in_sizes; (void)n_in; (void)out_size;
    const float* A = (const float*)d_in[0];
    const float* B = (const float*)d_in[1];
    float* C = (float*)d_out;

    cvtA_kernel<<<2048, 256>>>(A);
    cvtB_kernel<<<dim3(NDIM / 32, KDIM / 32, BATCH), dim3(32, 8)>>>(B);

    void *pAh = nullptr, *pBh = nullptr;
    cudaGetSymbolAddress(&pAh, g_Ah);
    cudaGetSymbolAddress(&pBh, g_Bh);

    void* fn = nullptr;
    cudaDriverEntryPointQueryResult qr;
    cudaGetDriverEntryPoint("cuTensorMapEncodeTiled", &fn, cudaEnableDefault, &qr);
    if (!fn) return;
    PFN_tmap_encode enc = (PFN_tmap_encode)fn;

    CUtensorMap mAh, mBh;
    make_map_f16(enc, &mAh, pAh, KDIM, (cuuint64_t)BATCH * MDIM, KC, TILE_M);
    make_map_f16(enc, &mBh, pBh, KDIM, (cuuint64_t)BATCH * NDIM, KC, TILE_N);

    cudaFuncSetAttribute(gemm_kernel, cudaFuncAttributeMaxDynamicSharedMemorySize,
                         SMEM_TOTAL);
    gemm_kernel<<<dim3(NDIM / TILE_N, MDIM / TILE_M, BATCH), 256, SMEM_TOTAL>>>(
        mAh, mBh, C);
}

// round 9
// speedup vs baseline: 7.0159x; 1.0912x over previous
#include <cuda_runtime.h>
#include <cuda.h>
#include <cuda_fp16.h>
#include <cstdint>
#include <cstddef>

// Problem dims (fixed by the dataset)
#define BATCH 4
#define MDIM 2048
#define NDIM 2048
#define KDIM 2048

// GEMM tiling: 128x64 tile, persistent CTAs, 2 CTAs/SM
#define TILE_M 128
#define TILE_N 64
#define KC 128                   // K per chunk: 2 SW128 atoms
#define CPT 16                   // chunks per tile (KDIM/KC)
#define STAGES 2
#define NTILES_TOTAL 2048        // (N/TILE_N) * (M/TILE_M) * BATCH = 32*16*4
#define GRID_X 304               // 2 * 152 SMs (GB300)

// Per-stage SMEM: A chunk 32KB (2 atom-tiles of 16KB) + B chunk 16KB (2 of 8KB)
#define OFF_AH 0
#define OFF_BH 32768
#define STAGE_BYTES 49152
#define SMEM_CTRL 1024
#define SMEM_TOTAL (SMEM_CTRL + STAGES * STAGE_BYTES)   // 99328 (x2 CTAs/SM)

// ---------------------------------------------------------------------------
// Scratch: fp16 of A [B,M,K]; B transposed to [B,N,K] (K-major)
// ---------------------------------------------------------------------------
__device__ alignas(1024) __half g_Ah[(size_t)BATCH * MDIM * KDIM];
__device__ alignas(1024) __half g_Bh[(size_t)BATCH * NDIM * KDIM];

// ---------------------------------------------------------------------------
// PTX helpers — sm_90-class only (NO 'a'-suffix features; target is sm_103)
// ---------------------------------------------------------------------------
__device__ __forceinline__ uint32_t smem_u32(const void* p) {
    uint32_t a;
    asm("{ .reg .u64 t; cvta.to.shared.u64 t, %1; cvt.u32.u64 %0, t; }"
        : "=r"(a) : "l"(p));
    return a;
}

#define MBARRIER_INIT(addr, cnt) \
    asm volatile("mbarrier.init.shared.b64 [%0], %1;" :: "r"(addr), "r"(cnt) : "memory")

#define MBARRIER_EXPECT_TX(addr, bytes) \
    asm volatile("mbarrier.arrive.expect_tx.shared.b64 _, [%0], %1;" \
                 :: "r"(addr), "r"(bytes) : "memory")

#define MBAR_WAIT(addr, parity) do {                                          \
    asm volatile(                                                             \
        "{\n\t.reg .pred P1;\n\t"                                             \
        "WAIT_LOOP_%=:\n\t"                                                   \
        "mbarrier.try_wait.parity.acquire.cta.shared::cta.b64 P1, [%0], %1, 0x989680;\n\t" \
        "@P1 bra.uni WAIT_DONE_%=;\n\t"                                       \
        "bra.uni WAIT_LOOP_%=;\n\t"                                           \
        "WAIT_DONE_%=:\n\t}"                                                  \
        :: "r"((uint32_t)(addr)), "r"((uint32_t)(parity)) : "memory");        \
} while (0)

__device__ __forceinline__ void tma2d(uint32_t smem_dst, const CUtensorMap* map,
                                      int x, int y, uint32_t mbar) {
    asm volatile(
        "cp.async.bulk.tensor.2d.shared::cta.global.tile.mbarrier::complete_tx::bytes "
        "[%0], [%1, {%2, %3}], [%4];"
        :: "r"(smem_dst), "l"(map), "r"(x), "r"(y), "r"(mbar)
        : "memory");
}

__device__ __forceinline__ void ldsm_x4(uint32_t* r, uint32_t addr) {
    asm volatile("ldmatrix.sync.aligned.m8n8.x4.shared.b16 {%0,%1,%2,%3}, [%4];"
                 : "=r"(r[0]), "=r"(r[1]), "=r"(r[2]), "=r"(r[3]) : "r"(addr));
}

// fp16 inputs, fp32 accumulate
__device__ __forceinline__ void mma_f32acc(float* d, const uint32_t* a,
                                           uint32_t b0, uint32_t b1) {
    asm volatile(
        "mma.sync.aligned.m16n8k16.row.col.f32.f16.f16.f32 "
        "{%0,%1,%2,%3}, {%4,%5,%6,%7}, {%8,%9}, {%0,%1,%2,%3};"
        : "+f"(d[0]), "+f"(d[1]), "+f"(d[2]), "+f"(d[3])
        : "r"(a[0]), "r"(a[1]), "r"(a[2]), "r"(a[3]), "r"(b0), "r"(b1));
}

// ---------------------------------------------------------------------------
// Fused convert kernel:
//   blocks [0, 16384): B[b][k][n] -> g_Bh[b][n][k] fp16 (32x32 tile transpose)
//   blocks [16384, 16896): A -> g_Ah fp16 (grid-stride)
// ---------------------------------------------------------------------------
#define NBLK_B 16384
#define NBLK_A 512

__global__ void cvt_fused_kernel(const float* __restrict__ a,
                                 const float* __restrict__ bsrc) {
    const int bx = blockIdx.x;
    const int tid = threadIdx.x;

    if (bx < NBLK_B) {
        __shared__ float t[32][33];
        const int nb = bx & 63;              // 64 n-tiles
        const int kb = (bx >> 6) & 63;       // 64 k-tiles
        const int b = bx >> 12;              // 4 batches
        const int n0 = nb * 32, k0 = kb * 32;
        const float* src = bsrc + (size_t)b * KDIM * NDIM;

        const int rr = tid >> 3, cc = (tid & 7) * 4;
        float4 v = *(const float4*)&src[(size_t)(k0 + rr) * NDIM + n0 + cc];
        t[rr][cc + 0] = v.x; t[rr][cc + 1] = v.y;
        t[rr][cc + 2] = v.z; t[rr][cc + 3] = v.w;
        __syncthreads();

        const int n = tid >> 3, kq = tid & 7;
        __half2 h01 = __floats2half2_rn(t[kq * 4 + 0][n], t[kq * 4 + 1][n]);
        __half2 h23 = __floats2half2_rn(t[kq * 4 + 2][n], t[kq * 4 + 3][n]);
        uint2 pk;
        pk.x = *reinterpret_cast<uint32_t*>(&h01);
        pk.y = *reinterpret_cast<uint32_t*>(&h23);
        const size_t off = (size_t)b * NDIM * KDIM + (size_t)(n0 + n) * KDIM
                         + k0 + kq * 4;
        *reinterpret_cast<uint2*>(&g_Bh[off]) = pk;
    } else {
        const size_t n4 = (size_t)BATCH * MDIM * KDIM / 4;
        const float4* a4 = (const float4*)a;
        uint2* hi = (uint2*)g_Ah;
        for (size_t i = (size_t)(bx - NBLK_B) * 256 + tid; i < n4;
             i += (size_t)NBLK_A * 256) {
            float4 v = a4[i];
            __half2 h01 = __floats2half2_rn(v.x, v.y);
            __half2 h23 = __floats2half2_rn(v.z, v.w);
            uint2 hv;
            hv.x = *reinterpret_cast<uint32_t*>(&h01);
            hv.y = *reinterpret_cast<uint32_t*>(&h23);
            hi[i] = hv;
        }
    }
}

// ---------------------------------------------------------------------------
// Persistent GEMM: each CTA loops over tiles (stride GRID_X).
// 128x64 tile, KC=128 chunks, 2-stage TMA pipeline continuous across tiles.
// 256 threads = 8 warps, warp grid 4(M) x 2(N), warp tile 32x32.
// ---------------------------------------------------------------------------
__device__ __forceinline__ void tile_coords(int t, int& rowA, int& rowB) {
    const int tn = t & 31;            // 32 N-tiles
    const int tm = (t >> 5) & 15;     // 16 M-tiles
    const int bb = t >> 9;            // batch
    rowA = bb * MDIM + tm * TILE_M;
    rowB = bb * NDIM + tn * TILE_N;
}

__global__ void __launch_bounds__(256, 2) gemm_kernel(
    const __grid_constant__ CUtensorMap mAh,
    const __grid_constant__ CUtensorMap mBh,
    float* __restrict__ C)
{
    extern __shared__ char smem[];
    const uint32_t sb = smem_u32(smem);
    const int tid = threadIdx.x;
    const int wid = tid >> 5;
    const int lane = tid & 31;
    const int warpM = wid & 3;
    const int warpN = wid >> 2;
    const int bx = blockIdx.x;

    const int ntiles = (NTILES_TOTAL - bx + GRID_X - 1) / GRID_X;
    const int nchunks = ntiles * CPT;

    if (tid == 0) {
        MBARRIER_INIT(sb + 0, 1);
        MBARRIER_INIT(sb + 8, 1);
        asm volatile("fence.proxy.async.shared::cta;" ::: "memory");
    }
    __syncthreads();

    // Prologue: fill both stages with tile 0, chunks 0 and 1
    if (tid == 0) {
        int rowA, rowB;
        tile_coords(bx, rowA, rowB);
#pragma unroll
        for (int s = 0; s < STAGES; s++) {
            const uint32_t st = sb + SMEM_CTRL + s * STAGE_BYTES;
            const int kk = s * KC;
            MBARRIER_EXPECT_TX(sb + 8 * s, (uint32_t)STAGE_BYTES);
            tma2d(st + OFF_AH,         &mAh, kk,      rowA, sb + 8 * s);
            tma2d(st + OFF_AH + 16384, &mAh, kk + 64, rowA, sb + 8 * s);
            tma2d(st + OFF_BH,         &mBh, kk,      rowB, sb + 8 * s);
            tma2d(st + OFF_BH + 8192,  &mBh, kk + 64, rowB, sb + 8 * s);
        }
    }

    // ldmatrix addressing (SW128 swizzle = XOR bits[6:4] with row&7)
    const int r15 = lane & 15;
    const int kh = lane >> 4;
    const uint32_t xorv = (uint32_t)((lane & 7) << 4);
    uint32_t kpart[4];
#pragma unroll
    for (int ks = 0; ks < 4; ks++)
        kpart[ks] = ((uint32_t)(ks * 32 + kh * 16)) ^ xorv;

    uint32_t aRowOff[2], bRowOff[2];
#pragma unroll
    for (int mt = 0; mt < 2; mt++)
        aRowOff[mt] = (uint32_t)(warpM * 32 + mt * 16 + r15) * 128;
#pragma unroll
    for (int ng = 0; ng < 2; ng++)
        bRowOff[ng] = (uint32_t)(warpN * 32 + ng * 16 + r15) * 128;

    int pf[STAGES] = {0, 0};

    for (int i = 0; i < ntiles; i++) {
        const int t = bx + i * GRID_X;

        float acc[2][4][4];
#pragma unroll
        for (int mt = 0; mt < 2; mt++)
#pragma unroll
            for (int nt = 0; nt < 4; nt++)
#pragma unroll
                for (int j = 0; j < 4; j++) acc[mt][nt][j] = 0.0f;

        for (int c = 0; c < CPT; c++) {
            const int s = c & 1;               // CPT even -> phase continuous
            MBAR_WAIT(sb + 8 * s, pf[s]);
            pf[s] ^= 1;
            const uint32_t st = sb + SMEM_CTRL + s * STAGE_BYTES;

#pragma unroll
            for (int ks = 0; ks < 8; ks++) {
                const int at = ks >> 2;        // which SW128 atom
                const int ik = ks & 3;
                uint32_t ah[2][4], bh[2][4];
#pragma unroll
                for (int mt = 0; mt < 2; mt++)
                    ldsm_x4(ah[mt], st + OFF_AH + at * 16384 + aRowOff[mt] + kpart[ik]);
#pragma unroll
                for (int ng = 0; ng < 2; ng++)
                    ldsm_x4(bh[ng], st + OFF_BH + at * 8192 + bRowOff[ng] + kpart[ik]);
#pragma unroll
                for (int mt = 0; mt < 2; mt++) {
#pragma unroll
                    for (int nt = 0; nt < 4; nt++) {
                        const int ng = nt >> 1;
                        const int o = nt & 1;
                        mma_f32acc(acc[mt][nt], ah[mt], bh[ng][o], bh[ng][o + 2]);
                    }
                }
            }

            __syncthreads();   // all warps done reading stage s
            if (tid == 0) {
                const int g2 = i * CPT + c + 2;
                if (g2 < nchunks) {
                    const int i2 = g2 >> 4;
                    const int c2 = g2 & 15;
                    int rowA2, rowB2;
                    tile_coords(bx + i2 * GRID_X, rowA2, rowB2);
                    const int kk = c2 * KC;
                    MBARRIER_EXPECT_TX(sb + 8 * s, (uint32_t)STAGE_BYTES);
                    tma2d(st + OFF_AH,         &mAh, kk,      rowA2, sb + 8 * s);
                    tma2d(st + OFF_AH + 16384, &mAh, kk + 64, rowA2, sb + 8 * s);
                    tma2d(st + OFF_BH,         &mBh, kk,      rowB2, sb + 8 * s);
                    tma2d(st + OFF_BH + 8192,  &mBh, kk + 64, rowB2, sb + 8 * s);
                }
            }
        }

        // Epilogue (registers only — overlaps with next tile's in-flight TMA)
        int rowA, rowB;
        tile_coords(t, rowA, rowB);
        const int bb = t >> 9;
        const int cRow0 = (rowA - bb * MDIM) + warpM * 32 + (lane >> 2);
        const int cCol0 = (rowB - bb * NDIM) + warpN * 32 + (lane & 3) * 2;
        float* Cb = C + (size_t)bb * MDIM * NDIM;
#pragma unroll
        for (int mt = 0; mt < 2; mt++) {
            const int r0 = cRow0 + mt * 16;
            float* rp0 = Cb + (size_t)r0 * NDIM + cCol0;
            float* rp1 = Cb + (size_t)(r0 + 8) * NDIM + cCol0;
#pragma unroll
            for (int nt = 0; nt < 4; nt++) {
                *reinterpret_cast<float2*>(rp0 + nt * 8) =
                    make_float2(acc[mt][nt][0], acc[mt][nt][1]);
                *reinterpret_cast<float2*>(rp1 + nt * 8) =
                    make_float2(acc[mt][nt][2], acc[mt][nt][3]);
            }
        }
    }
}

// ---------------------------------------------------------------------------
// Host launch
// ---------------------------------------------------------------------------
typedef CUresult (*PFN_tmap_encode)(
    CUtensorMap*, CUtensorMapDataType, cuuint32_t, void*,
    const cuuint64_t*, const cuuint64_t*, const cuuint32_t*, const cuuint32_t*,
    CUtensorMapInterleave, CUtensorMapSwizzle, CUtensorMapL2promotion,
    CUtensorMapFloatOOBfill);

static void make_map_f16(PFN_tmap_encode enc, CUtensorMap* m, void* base,
                         cuuint64_t dim0, cuuint64_t dim1,
                         cuuint32_t box0, cuuint32_t box1) {
    cuuint64_t gd[2] = {dim0, dim1};
    cuuint64_t gs[1] = {dim0 * sizeof(__half)};
    cuuint32_t bd[2] = {box0, box1};
    cuuint32_t es[2] = {1, 1};
    enc(m, CU_TENSOR_MAP_DATA_TYPE_FLOAT16, 2, base, gd, gs, bd, es,
        CU_TENSOR_MAP_INTERLEAVE_NONE, CU_TENSOR_MAP_SWIZZLE_128B,
        CU_TENSOR_MAP_L2_PROMOTION_L2_128B, CU_TENSOR_MAP_FLOAT_OOB_FILL_NONE);
}

extern "C" void kernel_launch(void* const* d_in, const int* in_sizes, int n_in,
                              void* d_out, int out_size) {
    (void)in_sizes; (void)n_in; (void)out_size;
    const float* A = (const float*)d_in[0];
    const float* B = (const float*)d_in[1];
    float* C = (float*)d_out;

    cvt_fused_kernel<<<NBLK_B + NBLK_A, 256>>>(A, B);

    void *pAh = nullptr, *pBh = nullptr;
    cudaGetSymbolAddress(&pAh, g_Ah);
    cudaGetSymbolAddress(&pBh, g_Bh);

    void* fn = nullptr;
    cudaDriverEntryPointQueryResult qr;
    cudaGetDriverEntryPoint("cuTensorMapEncodeTiled", &fn, cudaEnableDefault, &qr);
    if (!fn) return;
    PFN_tmap_encode enc = (PFN_tmap_encode)fn;

    CUtensorMap mAh, mBh;
    make_map_f16(enc, &mAh, pAh, KDIM, (cuuint64_t)BATCH * MDIM, 64, TILE_M);
    make_map_f16(enc, &mBh, pBh, KDIM, (cuuint64_t)BATCH * NDIM, 64, TILE_N);

    cudaFuncSetAttribute(gemm_kernel, cudaFuncAttributeMaxDynamicSharedMemorySize,
                         SMEM_TOTAL);
    gemm_kernel<<<GRID_X, 256, SMEM_TOTAL>>>(mAh, mBh, C);
}